// round 13
// baseline (speedup 1.0000x reference)
#include <cuda_runtime.h>
#include <cuda_fp16.h>
#include <cstdint>

// ============================================================================
// GridNeRF forward: register-chained mma.sync.m16n8k16, single fp16 operands,
// M=32 per warp. Hashgrid gathers + half the sincos hoisted out of the
// lane-half branch => convergent 32-lane issue (R12 was 2x serial 16-lane).
// ============================================================================

constexpr int TSZ = 1 << 19;

constexpr int sW1 = 56, sW2 = 72, sW3 = 88, sW4 = 72;   // elem strides [N][K]
constexpr int oW1 = 0;
constexpr int oW2 = oW1 + 64 * sW1;
constexpr int oW3 = oW2 + 72 * sW2;
constexpr int oW4 = oW3 + 64 * sW3;
constexpr int W_ELEMS = oW4 + 8 * sW4;  // 14976 elems = 29952 B

__device__ __align__(16) __half g_w[W_ELEMS];
__device__ __align__(16) float g_b2[72];
__device__ __align__(16) float g_b4[8];

constexpr int oSB2B = 29952;
constexpr int oSB4B = 30240;
constexpr int oSTB  = 30272;              // per-warp staging: 2 tiles x 2304 B
constexpr int SMEM_DYN = oSTB + 8 * 4608; // 67136

// ---------------- PTX helpers ----------------
__device__ __forceinline__ uint32_t smem_u32(const void* p) {
    uint32_t a;
    asm("{ .reg .u64 t; cvta.to.shared.u64 t, %1; cvt.u32.u64 %0, t; }"
        : "=r"(a) : "l"(p));
    return a;
}
__device__ __forceinline__ void ldsm4(uint32_t* r, uint32_t addr) {
    asm volatile("ldmatrix.sync.aligned.m8n8.x4.shared.b16 {%0,%1,%2,%3}, [%4];"
        : "=r"(r[0]), "=r"(r[1]), "=r"(r[2]), "=r"(r[3]) : "r"(addr));
}
__device__ __forceinline__ void ldsm2(uint32_t& r0, uint32_t& r1, uint32_t addr) {
    asm volatile("ldmatrix.sync.aligned.m8n8.x2.shared.b16 {%0,%1}, [%2];"
        : "=r"(r0), "=r"(r1) : "r"(addr));
}
#define MMA4(c, a, b0_, b1_) \
    asm volatile("mma.sync.aligned.m16n8k16.row.col.f32.f16.f16.f32 " \
        "{%0,%1,%2,%3},{%4,%5,%6,%7},{%8,%9},{%0,%1,%2,%3};" \
        : "+f"((c)[0]), "+f"((c)[1]), "+f"((c)[2]), "+f"((c)[3]) \
        : "r"((a)[0]), "r"((a)[1]), "r"((a)[2]), "r"((a)[3]), "r"(b0_), "r"(b1_))

__device__ __forceinline__ void pass2d(float* c0, float* c1,
    const uint32_t (*a0)[4], const uint32_t (*a1t)[4], int k0, uint32_t b_addr)
{
    uint32_t bb[4];
    ldsm4(bb, b_addr);
    MMA4(c0, a0[k0], bb[0], bb[1]);
    MMA4(c1, a1t[k0], bb[0], bb[1]);
    MMA4(c0, a0[k0 + 1], bb[2], bb[3]);
    MMA4(c1, a1t[k0 + 1], bb[2], bb[3]);
}
__device__ __forceinline__ void pass1d(float* c0, float* c1,
    const uint32_t* a0, const uint32_t* a1t, uint32_t b_addr)
{
    uint32_t r0, r1;
    ldsm2(r0, r1, b_addr);
    MMA4(c0, a0, r0, r1);
    MMA4(c1, a1t, r0, r1);
}

__device__ __forceinline__ uint32_t f16r(float a, float b) {
    __half2 h = __floats2half2_rn(fmaxf(a, 0.0f), fmaxf(b, 0.0f));
    return *reinterpret_cast<uint32_t*>(&h);
}

// ---------------- weight prep ----------------
__global__ void prep_weights(const float* __restrict__ dw1, const float* __restrict__ db1,
                             const float* __restrict__ dw2, const float* __restrict__ db2,
                             const float* __restrict__ rw1, const float* __restrict__ rb1,
                             const float* __restrict__ rw2, const float* __restrict__ rb2)
{
    const int tid = threadIdx.x;
    for (int i = tid; i < W_ELEMS; i += 256) g_w[i] = __float2half_rn(0.0f);
    __syncthreads();
    for (int i = tid; i < 64 * 48; i += 256) {
        int nn = i / 48, k = i % 48;
        float w;
        if (k < 27)       w = dw1[k * 64 + nn];
        else if (k == 27) w = db1[nn];
        else              w = dw1[(k - 1) * 64 + nn];
        g_w[oW1 + nn * sW1 + k] = __float2half_rn(w);
    }
    for (int i = tid; i < 65 * 64; i += 256) {
        int nn = i / 64, k = i % 64;
        float w = (nn < 64) ? dw2[k * 65 + nn + 1] : dw2[k * 65];
        g_w[oW2 + nn * sW2 + k] = __float2half_rn(w);
    }
    for (int i = tid; i < 64 * 74; i += 256) {
        int nn = i / 74, k = i % 74;
        float w = (k < 73) ? rw1[k * 64 + nn] : rb1[nn];
        g_w[oW3 + nn * sW3 + k] = __float2half_rn(w);
    }
    for (int i = tid; i < 3 * 64; i += 256) {
        int nn = i / 64, k = i % 64;
        g_w[oW4 + nn * sW4 + k] = __float2half_rn(rw2[k * 3 + nn]);
    }
    if (tid < 72) g_b2[tid] = (tid < 64) ? db2[tid + 1] : ((tid == 64) ? db2[0] : 0.0f);
    if (tid < 8)  g_b4[tid] = (tid < 3) ? rb2[tid] : 0.0f;
}

__device__ __forceinline__ void put_st2(char* H, uint32_t rbase, int c, float a, float b) {
    __half2 h = __floats2half2_rn(a, b);
    *(uint32_t*)(H + rbase + c * 2) = *reinterpret_cast<uint32_t*>(&h);
}

// ---------------- branchless hashgrid gather (one level) ----------------
__device__ __forceinline__ void gather_level(
    const float* __restrict__ tb, float res,
    float x01x, float x01y, float x01z, float& g0, float& g1)
{
    const float pxx = x01x * res, pyy = x01y * res, pzz = x01z * res;
    const float fx = floorf(pxx), fy = floorf(pyy), fz = floorf(pzz);
    const float tx = pxx - fx, ty = pyy - fy, tz = pzz - fz;
    const float wx = tx * tx * (3.0f - 2.0f * tx);
    const float wy = ty * ty * (3.0f - 2.0f * ty);
    const float wz = tz * tz * (3.0f - 2.0f * tz);
    const unsigned cx = (unsigned)fx, cy = (unsigned)fy, cz = (unsigned)fz;
    const unsigned ay0 = cy * 2654435761u, ay1 = ay0 + 2654435761u;
    const unsigned az0 = cz * 805459861u,  az1 = az0 + 805459861u;
    const unsigned mms[4] = {ay0 ^ az0, ay1 ^ az0, ay0 ^ az1, ay1 ^ az1};
    const float cws[4] = {(1.0f - wy) * (1.0f - wz), wy * (1.0f - wz),
                          (1.0f - wy) * wz,          wy * wz};
    float f0 = 0.0f, f1 = 0.0f;
    #pragma unroll
    for (int q = 0; q < 4; q++) {
        const unsigned i0 = (cx ^ mms[q]) & (unsigned)(TSZ - 1);
        const unsigned i1 = ((cx + 1u) ^ mms[q]) & (unsigned)(TSZ - 1);
        const float2 t0 = __ldg(reinterpret_cast<const float2*>(tb + 2u * i0));
        const float2 t1 = __ldg(reinterpret_cast<const float2*>(tb + 2u * i1));
        const float wa = (1.0f - wx) * cws[q], wb = wx * cws[q];
        f0 = fmaf(t0.x, wa, f0);
        f1 = fmaf(t0.y, wa, f1);
        f0 = fmaf(t1.x, wb, f0);
        f1 = fmaf(t1.y, wb, f1);
    }
    g0 = f0; g1 = f1;
}

// ---------------- encoding: convergent gathers + split fourier/SH ----------------
__device__ __forceinline__ void encode_tile(
    char* stH, uint32_t rbase, int half, int p,
    const float* __restrict__ x, const float* __restrict__ v,
    const float* __restrict__ table)
{
    const float px0 = x[3 * p], px1 = x[3 * p + 1], px2 = x[3 * p + 2];
    const float x01x = (px0 + 1.0f) * 0.5f;
    const float x01y = (px1 + 1.0f) * 0.5f;
    const float x01z = (px2 + 1.0f) * 0.5f;

    // --- convergent: 2 grid levels per lane-half (levels half*2, half*2+1) ---
    const float resA = half ? 56.0f : 33.0f;
    const float resB = half ? 74.0f : 43.0f;
    const float* tbA = table + (size_t)(half * 2) * (TSZ * 2);
    float g0a, g1a, g0b, g1b;
    gather_level(tbA,             resA, x01x, x01y, x01z, g0a, g1a);
    gather_level(tbA + (TSZ * 2), resB, x01x, x01y, x01z, g0b, g1b);

    // --- convergent: 6 sincos on (half ? z : x) ---
    const float pc = half ? px2 : px0;
    float s6[6], c6[6];
    {
        float fm = 1.0f;
        #pragma unroll
        for (int fr = 0; fr < 6; fr++) {
            __sincosf(pc * fm, &s6[fr], &c6[fr]);
            fm *= 2.0f;
        }
    }

    // --- convergent stores: grid feats (cols 40..43 for half0, 44..47 for half1) ---
    put_st2(stH, rbase, 40 + half * 4, g0a, g1a);
    put_st2(stH, rbase, 42 + half * 4, g0b, g1b);

    if (half == 0) {
        float e[28];
        e[0] = px0; e[1] = px1; e[2] = px2;
        #pragma unroll
        for (int fr = 0; fr < 6; fr++) { e[3 + fr] = s6[fr]; e[9 + fr] = c6[fr]; }
        // y fourier
        float fm = 1.0f;
        #pragma unroll
        for (int fr = 0; fr < 6; fr++) {
            __sincosf(px1 * fm, &e[15 + fr], &e[21 + fr]);
            fm *= 2.0f;
        }
        e[27] = 1.0f;  // L1 bias column
        #pragma unroll
        for (int q = 0; q < 14; q++)
            put_st2(stH, rbase, 2 * q, e[2 * q], e[2 * q + 1]);
    } else {
        // z fourier: cols 28..39
        #pragma unroll
        for (int q = 0; q < 3; q++)
            put_st2(stH, rbase, 28 + 2 * q, s6[2 * q], s6[2 * q + 1]);
        #pragma unroll
        for (int q = 0; q < 3; q++)
            put_st2(stH, rbase, 34 + 2 * q, c6[2 * q], c6[2 * q + 1]);
        // SH -> cols 48..56; 1.0 (L3 bias) at 57
        const float vx = v[3 * p], vy = v[3 * p + 1], vz = v[3 * p + 2];
        put_st2(stH, rbase, 48, 0.28209479177387814f, -0.4886025119029199f * vy);
        put_st2(stH, rbase, 50,  0.4886025119029199f * vz, -0.4886025119029199f * vx);
        put_st2(stH, rbase, 52,  1.0925484305920792f * vx * vy,
                                -1.0925484305920792f * vy * vz);
        put_st2(stH, rbase, 54,  0.9461746957575601f * vz * vz - 0.31539156525252005f,
                                -1.0925484305920792f * vx * vz);
        put_st2(stH, rbase, 56,  0.5462742152960396f * (vx * vx - vy * vy), 1.0f);
    }
}

__device__ __forceinline__ float sigmoidf_(float z) {
    return 1.0f / (1.0f + __expf(-z));
}

// ---------------- main kernel ----------------
__global__ void __launch_bounds__(256, 2) nerf_mma9(
    const float* __restrict__ x, const float* __restrict__ v,
    const float* __restrict__ table, float* __restrict__ out, int n)
{
    extern __shared__ __align__(16) unsigned char S[];
    const int tid = threadIdx.x, wid = tid >> 5, lane = tid & 31;

    for (int i = tid; i < 29952 / 16; i += 256)
        ((uint4*)S)[i] = ((const uint4*)g_w)[i];
    float* sB2 = (float*)(S + oSB2B);
    float* sB4 = (float*)(S + oSB4B);
    if (tid < 72) sB2[tid] = g_b2[tid];
    if (tid < 8)  sB4[tid] = g_b4[tid];
    __syncthreads();

    const uint32_t uS = smem_u32(S);
    const int g = lane >> 2, t2 = (lane & 3) * 2;
    const int row = lane >> 1, half = lane & 1;

    char* st0 = (char*)(S + oSTB + wid * 4608);
    char* st1 = st0 + 2304;
    const uint32_t uSt0 = uS + oSTB + wid * 4608;
    const uint32_t uSt1 = uSt0 + 2304;
    const uint32_t rbase = (uint32_t)row * 144;

    const uint32_t aofs   = (lane & 15) * 144 + (lane >> 4) * 16;
    const uint32_t bo112  = (lane & 7) * 112 + (lane >> 3) * 16;
    const uint32_t bo112b = (lane & 7) * 112 + ((lane >> 3) & 1) * 16;
    const uint32_t bo144  = (lane & 7) * 144 + (lane >> 3) * 16;
    const uint32_t bo176  = (lane & 7) * 176 + (lane >> 3) * 16;
    const uint32_t bo176b = (lane & 7) * 176 + ((lane >> 3) & 1) * 16;

    const uint32_t uW1  = uS + oW1 * 2 + bo112;
    const uint32_t uW1b = uS + oW1 * 2 + 64 + bo112b;
    const uint32_t uW2  = uS + oW2 * 2 + bo144;
    const uint32_t uW3  = uS + oW3 * 2 + bo176;
    const uint32_t uW3b = uS + oW3 * 2 + 128 + bo176b;
    const uint32_t uW4  = uS + oW4 * 2 + bo144;

    // one-time: zero staging cols 58..63 of both tiles
    if (half == 0) {
        put_st2(st0, rbase, 58, 0.0f, 0.0f);
        put_st2(st0, rbase, 60, 0.0f, 0.0f);
        put_st2(st0, rbase, 62, 0.0f, 0.0f);
        put_st2(st1, rbase, 58, 0.0f, 0.0f);
        put_st2(st1, rbase, 60, 0.0f, 0.0f);
        put_st2(st1, rbase, 62, 0.0f, 0.0f);
    }

    const int npairs = n >> 5;
    const int totw = gridDim.x * 8;

    for (int pair = blockIdx.x * 8 + wid; pair < npairs; pair += totw) {
        const int t0 = 2 * pair, t1 = 2 * pair + 1;

        encode_tile(st0, rbase, half, t0 * 16 + row, x, v, table);
        encode_tile(st1, rbase, half, t1 * 16 + row, x, v, table);
        __syncwarp();

        // ---------------- A1 fragments ----------------
        uint32_t a1[2][3][4];
        #pragma unroll
        for (int k = 0; k < 3; k++) {
            ldsm4(a1[0][k], uSt0 + aofs + 32 * k);
            ldsm4(a1[1][k], uSt1 + aofs + 32 * k);
        }

        // ---------------- L1 ----------------
        uint32_t a2[2][4][4];
        #pragma unroll
        for (int m = 0; m < 4; m++) {
            float c[2][2][4];   // [u][tile]
            #pragma unroll
            for (int u = 0; u < 2; u++) {
                const uint32_t jb = (2 * m + u) * (8 * 112);
                float *c0 = c[u][0], *c1 = c[u][1];
                #pragma unroll
                for (int q = 0; q < 4; q++) { c0[q] = 0.0f; c1[q] = 0.0f; }
                pass2d(c0, c1, a1[0], a1[1], 0, uW1 + jb);
                pass1d(c0, c1, a1[0][2], a1[1][2], uW1b + jb);
            }
            #pragma unroll
            for (int tt = 0; tt < 2; tt++) {
                a2[tt][m][0] = f16r(c[0][tt][0], c[0][tt][1]);
                a2[tt][m][1] = f16r(c[0][tt][2], c[0][tt][3]);
                a2[tt][m][2] = f16r(c[1][tt][0], c[1][tt][1]);
                a2[tt][m][3] = f16r(c[1][tt][2], c[1][tt][3]);
            }
        }

        // ---------------- L2 ----------------
        uint32_t a3[2][5][4];
        #pragma unroll
        for (int m = 0; m < 4; m++) {
            float c[2][2][4];
            #pragma unroll
            for (int u = 0; u < 2; u++) {
                const int j = 2 * m + u;
                const uint32_t jb = j * (8 * 144);
                float *c0 = c[u][0], *c1 = c[u][1];
                const float2 bb = *(const float2*)(sB2 + 8 * j + t2);
                c0[0] = bb.x; c0[1] = bb.y; c0[2] = bb.x; c0[3] = bb.y;
                c1[0] = bb.x; c1[1] = bb.y; c1[2] = bb.x; c1[3] = bb.y;
                pass2d(c0, c1, a2[0], a2[1], 0, uW2 + jb);
                pass2d(c0, c1, a2[0], a2[1], 2, uW2 + jb + 64);
            }
            #pragma unroll
            for (int tt = 0; tt < 2; tt++) {
                a3[tt][m][0] = f16r(c[0][tt][0], c[0][tt][1]);
                a3[tt][m][1] = f16r(c[0][tt][2], c[0][tt][3]);
                a3[tt][m][2] = f16r(c[1][tt][0], c[1][tt][1]);
                a3[tt][m][3] = f16r(c[1][tt][2], c[1][tt][3]);
            }
        }
        {   // sigma n-tile
            float c0[4], c1[4];
            const float2 bb = *(const float2*)(sB2 + 64 + t2);
            c0[0] = bb.x; c0[1] = bb.y; c0[2] = bb.x; c0[3] = bb.y;
            c1[0] = bb.x; c1[1] = bb.y; c1[2] = bb.x; c1[3] = bb.y;
            const uint32_t jb = 8 * (8 * 144);
            pass2d(c0, c1, a2[0], a2[1], 0, uW2 + jb);
            pass2d(c0, c1, a2[0], a2[1], 2, uW2 + jb + 64);
            if ((lane & 3) == 0) {
                out[t0 * 16 + g]     = __expf(c0[0]);
                out[t0 * 16 + g + 8] = __expf(c0[2]);
                out[t1 * 16 + g]     = __expf(c1[0]);
                out[t1 * 16 + g + 8] = __expf(c1[2]);
            }
        }
        ldsm4(a3[0][4], uSt0 + aofs + 96);
        ldsm4(a3[1][4], uSt1 + aofs + 96);

        // ---------------- L3 ----------------
        uint32_t a4[2][4][4];
        #pragma unroll
        for (int m = 0; m < 4; m++) {
            float c[2][2][4];
            #pragma unroll
            for (int u = 0; u < 2; u++) {
                const uint32_t jb = (2 * m + u) * (8 * 176);
                float *c0 = c[u][0], *c1 = c[u][1];
                #pragma unroll
                for (int q = 0; q < 4; q++) { c0[q] = 0.0f; c1[q] = 0.0f; }
                pass2d(c0, c1, a3[0], a3[1], 0, uW3 + jb);
                pass2d(c0, c1, a3[0], a3[1], 2, uW3 + jb + 64);
                pass1d(c0, c1, a3[0][4], a3[1][4], uW3b + jb);
            }
            #pragma unroll
            for (int tt = 0; tt < 2; tt++) {
                a4[tt][m][0] = f16r(c[0][tt][0], c[0][tt][1]);
                a4[tt][m][1] = f16r(c[0][tt][2], c[0][tt][3]);
                a4[tt][m][2] = f16r(c[1][tt][0], c[1][tt][1]);
                a4[tt][m][3] = f16r(c[1][tt][2], c[1][tt][3]);
            }
        }

        // ---------------- L4 + rgb ----------------
        {
            float c0[4], c1[4];
            const float2 bb = *(const float2*)(sB4 + t2);
            c0[0] = bb.x; c0[1] = bb.y; c0[2] = bb.x; c0[3] = bb.y;
            c1[0] = bb.x; c1[1] = bb.y; c1[2] = bb.x; c1[3] = bb.y;
            pass2d(c0, c1, a4[0], a4[1], 0, uW4);
            pass2d(c0, c1, a4[0], a4[1], 2, uW4 + 64);
            const int p0 = t0 * 16 + g, p1 = t1 * 16 + g;
            if ((lane & 3) == 0) {
                out[n + 3 * p0 + 0]       = sigmoidf_(c0[0]);
                out[n + 3 * p0 + 1]       = sigmoidf_(c0[1]);
                out[n + 3 * (p0 + 8) + 0] = sigmoidf_(c0[2]);
                out[n + 3 * (p0 + 8) + 1] = sigmoidf_(c0[3]);
                out[n + 3 * p1 + 0]       = sigmoidf_(c1[0]);
                out[n + 3 * p1 + 1]       = sigmoidf_(c1[1]);
                out[n + 3 * (p1 + 8) + 0] = sigmoidf_(c1[2]);
                out[n + 3 * (p1 + 8) + 1] = sigmoidf_(c1[3]);
            } else if ((lane & 3) == 1) {
                out[n + 3 * p0 + 2]       = sigmoidf_(c0[0]);
                out[n + 3 * (p0 + 8) + 2] = sigmoidf_(c0[2]);
                out[n + 3 * p1 + 2]       = sigmoidf_(c1[0]);
                out[n + 3 * (p1 + 8) + 2] = sigmoidf_(c1[2]);
            }
        }
        __syncwarp();
    }
}

extern "C" void kernel_launch(void* const* d_in, const int* in_sizes, int n_in,
                              void* d_out, int out_size)
{
    const float* x     = (const float*)d_in[0];
    const float* v     = (const float*)d_in[1];
    const float* table = (const float*)d_in[3];
    const float* dw1   = (const float*)d_in[4];
    const float* db1   = (const float*)d_in[5];
    const float* dw2   = (const float*)d_in[6];
    const float* db2   = (const float*)d_in[7];
    const float* rw1   = (const float*)d_in[8];
    const float* rb1   = (const float*)d_in[9];
    const float* rw2   = (const float*)d_in[10];
    const float* rb2   = (const float*)d_in[11];
    float* out = (float*)d_out;

    const int n = in_sizes[0] / 3;

    cudaFuncSetAttribute(nerf_mma9, cudaFuncAttributeMaxDynamicSharedMemorySize, SMEM_DYN);

    prep_weights<<<1, 256>>>(dw1, db1, dw2, db2, rw1, rb1, rw2, rb2);
    nerf_mma9<<<296, 256, SMEM_DYN>>>(x, v, table, out, n);
}

// round 14
// speedup vs baseline: 1.0541x; 1.0541x over previous
#include <cuda_runtime.h>
#include <cuda_fp16.h>
#include <cstdint>

// ============================================================================
// GridNeRF forward: register-chained mma.sync.m16n8k16, single fp16 operands,
// M=32 per warp (R12 structure). Both hashgrid levels per lane-half fused:
// all 16 corner LDGs issue back-to-back (2x gather MLP vs R12).
// ============================================================================

constexpr int TSZ = 1 << 19;

constexpr int sW1 = 56, sW2 = 72, sW3 = 88, sW4 = 72;   // elem strides [N][K]
constexpr int oW1 = 0;
constexpr int oW2 = oW1 + 64 * sW1;
constexpr int oW3 = oW2 + 72 * sW2;
constexpr int oW4 = oW3 + 64 * sW3;
constexpr int W_ELEMS = oW4 + 8 * sW4;  // 14976 elems = 29952 B

__device__ __align__(16) __half g_w[W_ELEMS];
__device__ __align__(16) float g_b2[72];
__device__ __align__(16) float g_b4[8];

constexpr int oSB2B = 29952;
constexpr int oSB4B = 30240;
constexpr int oSTB  = 30272;              // per-warp staging: 2 tiles x 2304 B
constexpr int SMEM_DYN = oSTB + 8 * 4608; // 67136

// ---------------- PTX helpers ----------------
__device__ __forceinline__ uint32_t smem_u32(const void* p) {
    uint32_t a;
    asm("{ .reg .u64 t; cvta.to.shared.u64 t, %1; cvt.u32.u64 %0, t; }"
        : "=r"(a) : "l"(p));
    return a;
}
__device__ __forceinline__ void ldsm4(uint32_t* r, uint32_t addr) {
    asm volatile("ldmatrix.sync.aligned.m8n8.x4.shared.b16 {%0,%1,%2,%3}, [%4];"
        : "=r"(r[0]), "=r"(r[1]), "=r"(r[2]), "=r"(r[3]) : "r"(addr));
}
__device__ __forceinline__ void ldsm2(uint32_t& r0, uint32_t& r1, uint32_t addr) {
    asm volatile("ldmatrix.sync.aligned.m8n8.x2.shared.b16 {%0,%1}, [%2];"
        : "=r"(r0), "=r"(r1) : "r"(addr));
}
#define MMA4(c, a, b0_, b1_) \
    asm volatile("mma.sync.aligned.m16n8k16.row.col.f32.f16.f16.f32 " \
        "{%0,%1,%2,%3},{%4,%5,%6,%7},{%8,%9},{%0,%1,%2,%3};" \
        : "+f"((c)[0]), "+f"((c)[1]), "+f"((c)[2]), "+f"((c)[3]) \
        : "r"((a)[0]), "r"((a)[1]), "r"((a)[2]), "r"((a)[3]), "r"(b0_), "r"(b1_))

__device__ __forceinline__ void pass2d(float* c0, float* c1,
    const uint32_t (*a0)[4], const uint32_t (*a1t)[4], int k0, uint32_t b_addr)
{
    uint32_t bb[4];
    ldsm4(bb, b_addr);
    MMA4(c0, a0[k0], bb[0], bb[1]);
    MMA4(c1, a1t[k0], bb[0], bb[1]);
    MMA4(c0, a0[k0 + 1], bb[2], bb[3]);
    MMA4(c1, a1t[k0 + 1], bb[2], bb[3]);
}
__device__ __forceinline__ void pass1d(float* c0, float* c1,
    const uint32_t* a0, const uint32_t* a1t, uint32_t b_addr)
{
    uint32_t r0, r1;
    ldsm2(r0, r1, b_addr);
    MMA4(c0, a0, r0, r1);
    MMA4(c1, a1t, r0, r1);
}

__device__ __forceinline__ uint32_t f16r(float a, float b) {
    __half2 h = __floats2half2_rn(fmaxf(a, 0.0f), fmaxf(b, 0.0f));
    return *reinterpret_cast<uint32_t*>(&h);
}

// ---------------- weight prep ----------------
__global__ void prep_weights(const float* __restrict__ dw1, const float* __restrict__ db1,
                             const float* __restrict__ dw2, const float* __restrict__ db2,
                             const float* __restrict__ rw1, const float* __restrict__ rb1,
                             const float* __restrict__ rw2, const float* __restrict__ rb2)
{
    const int tid = threadIdx.x;
    for (int i = tid; i < W_ELEMS; i += 256) g_w[i] = __float2half_rn(0.0f);
    __syncthreads();
    for (int i = tid; i < 64 * 48; i += 256) {
        int nn = i / 48, k = i % 48;
        float w;
        if (k < 27)       w = dw1[k * 64 + nn];
        else if (k == 27) w = db1[nn];
        else              w = dw1[(k - 1) * 64 + nn];
        g_w[oW1 + nn * sW1 + k] = __float2half_rn(w);
    }
    for (int i = tid; i < 65 * 64; i += 256) {
        int nn = i / 64, k = i % 64;
        float w = (nn < 64) ? dw2[k * 65 + nn + 1] : dw2[k * 65];
        g_w[oW2 + nn * sW2 + k] = __float2half_rn(w);
    }
    for (int i = tid; i < 64 * 74; i += 256) {
        int nn = i / 74, k = i % 74;
        float w = (k < 73) ? rw1[k * 64 + nn] : rb1[nn];
        g_w[oW3 + nn * sW3 + k] = __float2half_rn(w);
    }
    for (int i = tid; i < 3 * 64; i += 256) {
        int nn = i / 64, k = i % 64;
        g_w[oW4 + nn * sW4 + k] = __float2half_rn(rw2[k * 3 + nn]);
    }
    if (tid < 72) g_b2[tid] = (tid < 64) ? db2[tid + 1] : ((tid == 64) ? db2[0] : 0.0f);
    if (tid < 8)  g_b4[tid] = (tid < 3) ? rb2[tid] : 0.0f;
}

__device__ __forceinline__ void put_st2(char* H, uint32_t rbase, int c, float a, float b) {
    __half2 h = __floats2half2_rn(a, b);
    *(uint32_t*)(H + rbase + c * 2) = *reinterpret_cast<uint32_t*>(&h);
}

// ---------------- fused two-level gather: 16 LDGs issued back-to-back ----------------
__device__ __forceinline__ void gather_two(
    const float* __restrict__ tbA, float resA,
    const float* __restrict__ tbB, float resB,
    float x01x, float x01y, float x01z,
    float& g0a, float& g1a, float& g0b, float& g1b)
{
    // ----- level A setup -----
    const float pxa = x01x * resA, pya = x01y * resA, pza = x01z * resA;
    const float fxa = floorf(pxa), fya = floorf(pya), fza = floorf(pza);
    const float txa = pxa - fxa, tya = pya - fya, tza = pza - fza;
    const float wxa = txa * txa * (3.0f - 2.0f * txa);
    const float wya = tya * tya * (3.0f - 2.0f * tya);
    const float wza = tza * tza * (3.0f - 2.0f * tza);
    const unsigned cxa = (unsigned)fxa, cya = (unsigned)fya, cza = (unsigned)fza;
    const unsigned ayA0 = cya * 2654435761u, ayA1 = ayA0 + 2654435761u;
    const unsigned azA0 = cza * 805459861u,  azA1 = azA0 + 805459861u;
    const unsigned mmsA[4] = {ayA0 ^ azA0, ayA1 ^ azA0, ayA0 ^ azA1, ayA1 ^ azA1};
    const float cwsA[4] = {(1.0f - wya) * (1.0f - wza), wya * (1.0f - wza),
                           (1.0f - wya) * wza,          wya * wza};
    // ----- level B setup -----
    const float pxb = x01x * resB, pyb = x01y * resB, pzb = x01z * resB;
    const float fxb = floorf(pxb), fyb = floorf(pyb), fzb = floorf(pzb);
    const float txb = pxb - fxb, tyb = pyb - fyb, tzb = pzb - fzb;
    const float wxb = txb * txb * (3.0f - 2.0f * txb);
    const float wyb = tyb * tyb * (3.0f - 2.0f * tyb);
    const float wzb = tzb * tzb * (3.0f - 2.0f * tzb);
    const unsigned cxb = (unsigned)fxb, cyb = (unsigned)fyb, czb = (unsigned)fzb;
    const unsigned ayB0 = cyb * 2654435761u, ayB1 = ayB0 + 2654435761u;
    const unsigned azB0 = czb * 805459861u,  azB1 = azB0 + 805459861u;
    const unsigned mmsB[4] = {ayB0 ^ azB0, ayB1 ^ azB0, ayB0 ^ azB1, ayB1 ^ azB1};
    const float cwsB[4] = {(1.0f - wyb) * (1.0f - wzb), wyb * (1.0f - wzb),
                           (1.0f - wyb) * wzb,          wyb * wzb};

    // ----- issue all 16 loads before consuming any -----
    float2 tA0[4], tA1[4], tB0[4], tB1[4];
    #pragma unroll
    for (int q = 0; q < 4; q++) {
        const unsigned iA0 = (cxa ^ mmsA[q]) & (unsigned)(TSZ - 1);
        const unsigned iA1 = ((cxa + 1u) ^ mmsA[q]) & (unsigned)(TSZ - 1);
        tA0[q] = __ldg(reinterpret_cast<const float2*>(tbA + 2u * iA0));
        tA1[q] = __ldg(reinterpret_cast<const float2*>(tbA + 2u * iA1));
    }
    #pragma unroll
    for (int q = 0; q < 4; q++) {
        const unsigned iB0 = (cxb ^ mmsB[q]) & (unsigned)(TSZ - 1);
        const unsigned iB1 = ((cxb + 1u) ^ mmsB[q]) & (unsigned)(TSZ - 1);
        tB0[q] = __ldg(reinterpret_cast<const float2*>(tbB + 2u * iB0));
        tB1[q] = __ldg(reinterpret_cast<const float2*>(tbB + 2u * iB1));
    }

    // ----- interpolate (same fmaf order per level as before -> bit-identical) -----
    float f0 = 0.0f, f1 = 0.0f;
    #pragma unroll
    for (int q = 0; q < 4; q++) {
        const float wa = (1.0f - wxa) * cwsA[q], wb = wxa * cwsA[q];
        f0 = fmaf(tA0[q].x, wa, f0);
        f1 = fmaf(tA0[q].y, wa, f1);
        f0 = fmaf(tA1[q].x, wb, f0);
        f1 = fmaf(tA1[q].y, wb, f1);
    }
    g0a = f0; g1a = f1;
    f0 = 0.0f; f1 = 0.0f;
    #pragma unroll
    for (int q = 0; q < 4; q++) {
        const float wa = (1.0f - wxb) * cwsB[q], wb = wxb * cwsB[q];
        f0 = fmaf(tB0[q].x, wa, f0);
        f1 = fmaf(tB0[q].y, wa, f1);
        f0 = fmaf(tB1[q].x, wb, f0);
        f1 = fmaf(tB1[q].y, wb, f1);
    }
    g0b = f0; g1b = f1;
}

// ---------------- encoding (R12 divergent structure, fused gathers) ----------------
__device__ __forceinline__ void encode_tile(
    char* stH, uint32_t rbase, int half, int p,
    const float* __restrict__ x, const float* __restrict__ v,
    const float* __restrict__ table)
{
    const float px0 = x[3 * p], px1 = x[3 * p + 1], px2 = x[3 * p + 2];
    const float x01x = (px0 + 1.0f) * 0.5f;
    const float x01y = (px1 + 1.0f) * 0.5f;
    const float x01z = (px2 + 1.0f) * 0.5f;
    if (half == 0) {
        // grid levels 0,1 -> cols 40..43 (fused, 16 LDG batched)
        float g0a, g1a, g0b, g1b;
        gather_two(table, 33.0f, table + 1 * (TSZ * 2), 43.0f,
                   x01x, x01y, x01z, g0a, g1a, g0b, g1b);
        float e[28];
        e[0] = px0; e[1] = px1; e[2] = px2;
        const float pv[2] = {px0, px1};
        #pragma unroll
        for (int d = 0; d < 2; d++) {
            float fm = 1.0f;
            #pragma unroll
            for (int fr = 0; fr < 6; fr++) {
                __sincosf(pv[d] * fm, &e[3 + d * 12 + fr], &e[9 + d * 12 + fr]);
                fm *= 2.0f;
            }
        }
        e[27] = 1.0f;  // L1 bias column
        #pragma unroll
        for (int q = 0; q < 14; q++)
            put_st2(stH, rbase, 2 * q, e[2 * q], e[2 * q + 1]);
        put_st2(stH, rbase, 40, g0a, g1a);
        put_st2(stH, rbase, 42, g0b, g1b);
    } else {
        // grid levels 2,3 -> cols 44..47 (fused, 16 LDG batched)
        float g0a, g1a, g0b, g1b;
        gather_two(table + 2 * (TSZ * 2), 56.0f, table + 3 * (TSZ * 2), 74.0f,
                   x01x, x01y, x01z, g0a, g1a, g0b, g1b);
        float e[12];   // fourier z: cols 28..39
        float fm = 1.0f;
        #pragma unroll
        for (int fr = 0; fr < 6; fr++) {
            __sincosf(px2 * fm, &e[fr], &e[6 + fr]);
            fm *= 2.0f;
        }
        #pragma unroll
        for (int q = 0; q < 6; q++)
            put_st2(stH, rbase, 28 + 2 * q, e[2 * q], e[2 * q + 1]);
        put_st2(stH, rbase, 44, g0a, g1a);
        put_st2(stH, rbase, 46, g0b, g1b);
        // SH -> cols 48..56; 1.0 (L3 bias) at 57
        const float vx = v[3 * p], vy = v[3 * p + 1], vz = v[3 * p + 2];
        put_st2(stH, rbase, 48, 0.28209479177387814f, -0.4886025119029199f * vy);
        put_st2(stH, rbase, 50,  0.4886025119029199f * vz, -0.4886025119029199f * vx);
        put_st2(stH, rbase, 52,  1.0925484305920792f * vx * vy,
                                -1.0925484305920792f * vy * vz);
        put_st2(stH, rbase, 54,  0.9461746957575601f * vz * vz - 0.31539156525252005f,
                                -1.0925484305920792f * vx * vz);
        put_st2(stH, rbase, 56,  0.5462742152960396f * (vx * vx - vy * vy), 1.0f);
    }
}

__device__ __forceinline__ float sigmoidf_(float z) {
    return 1.0f / (1.0f + __expf(-z));
}

// ---------------- main kernel ----------------
__global__ void __launch_bounds__(256, 2) nerf_mma10(
    const float* __restrict__ x, const float* __restrict__ v,
    const float* __restrict__ table, float* __restrict__ out, int n)
{
    extern __shared__ __align__(16) unsigned char S[];
    const int tid = threadIdx.x, wid = tid >> 5, lane = tid & 31;

    for (int i = tid; i < 29952 / 16; i += 256)
        ((uint4*)S)[i] = ((const uint4*)g_w)[i];
    float* sB2 = (float*)(S + oSB2B);
    float* sB4 = (float*)(S + oSB4B);
    if (tid < 72) sB2[tid] = g_b2[tid];
    if (tid < 8)  sB4[tid] = g_b4[tid];
    __syncthreads();

    const uint32_t uS = smem_u32(S);
    const int g = lane >> 2, t2 = (lane & 3) * 2;
    const int row = lane >> 1, half = lane & 1;

    char* st0 = (char*)(S + oSTB + wid * 4608);
    char* st1 = st0 + 2304;
    const uint32_t uSt0 = uS + oSTB + wid * 4608;
    const uint32_t uSt1 = uSt0 + 2304;
    const uint32_t rbase = (uint32_t)row * 144;

    const uint32_t aofs   = (lane & 15) * 144 + (lane >> 4) * 16;
    const uint32_t bo112  = (lane & 7) * 112 + (lane >> 3) * 16;
    const uint32_t bo112b = (lane & 7) * 112 + ((lane >> 3) & 1) * 16;
    const uint32_t bo144  = (lane & 7) * 144 + (lane >> 3) * 16;
    const uint32_t bo176  = (lane & 7) * 176 + (lane >> 3) * 16;
    const uint32_t bo176b = (lane & 7) * 176 + ((lane >> 3) & 1) * 16;

    const uint32_t uW1  = uS + oW1 * 2 + bo112;
    const uint32_t uW1b = uS + oW1 * 2 + 64 + bo112b;
    const uint32_t uW2  = uS + oW2 * 2 + bo144;
    const uint32_t uW3  = uS + oW3 * 2 + bo176;
    const uint32_t uW3b = uS + oW3 * 2 + 128 + bo176b;
    const uint32_t uW4  = uS + oW4 * 2 + bo144;

    // one-time: zero staging cols 58..63 of both tiles
    if (half == 0) {
        put_st2(st0, rbase, 58, 0.0f, 0.0f);
        put_st2(st0, rbase, 60, 0.0f, 0.0f);
        put_st2(st0, rbase, 62, 0.0f, 0.0f);
        put_st2(st1, rbase, 58, 0.0f, 0.0f);
        put_st2(st1, rbase, 60, 0.0f, 0.0f);
        put_st2(st1, rbase, 62, 0.0f, 0.0f);
    }

    const int npairs = n >> 5;
    const int totw = gridDim.x * 8;

    for (int pair = blockIdx.x * 8 + wid; pair < npairs; pair += totw) {
        const int t0 = 2 * pair, t1 = 2 * pair + 1;

        encode_tile(st0, rbase, half, t0 * 16 + row, x, v, table);
        encode_tile(st1, rbase, half, t1 * 16 + row, x, v, table);
        __syncwarp();

        // ---------------- A1 fragments ----------------
        uint32_t a1[2][3][4];
        #pragma unroll
        for (int k = 0; k < 3; k++) {
            ldsm4(a1[0][k], uSt0 + aofs + 32 * k);
            ldsm4(a1[1][k], uSt1 + aofs + 32 * k);
        }

        // ---------------- L1 ----------------
        uint32_t a2[2][4][4];
        #pragma unroll
        for (int m = 0; m < 4; m++) {
            float c[2][2][4];   // [u][tile]
            #pragma unroll
            for (int u = 0; u < 2; u++) {
                const uint32_t jb = (2 * m + u) * (8 * 112);
                float *c0 = c[u][0], *c1 = c[u][1];
                #pragma unroll
                for (int q = 0; q < 4; q++) { c0[q] = 0.0f; c1[q] = 0.0f; }
                pass2d(c0, c1, a1[0], a1[1], 0, uW1 + jb);
                pass1d(c0, c1, a1[0][2], a1[1][2], uW1b + jb);
            }
            #pragma unroll
            for (int tt = 0; tt < 2; tt++) {
                a2[tt][m][0] = f16r(c[0][tt][0], c[0][tt][1]);
                a2[tt][m][1] = f16r(c[0][tt][2], c[0][tt][3]);
                a2[tt][m][2] = f16r(c[1][tt][0], c[1][tt][1]);
                a2[tt][m][3] = f16r(c[1][tt][2], c[1][tt][3]);
            }
        }

        // ---------------- L2 ----------------
        uint32_t a3[2][5][4];
        #pragma unroll
        for (int m = 0; m < 4; m++) {
            float c[2][2][4];
            #pragma unroll
            for (int u = 0; u < 2; u++) {
                const int j = 2 * m + u;
                const uint32_t jb = j * (8 * 144);
                float *c0 = c[u][0], *c1 = c[u][1];
                const float2 bb = *(const float2*)(sB2 + 8 * j + t2);
                c0[0] = bb.x; c0[1] = bb.y; c0[2] = bb.x; c0[3] = bb.y;
                c1[0] = bb.x; c1[1] = bb.y; c1[2] = bb.x; c1[3] = bb.y;
                pass2d(c0, c1, a2[0], a2[1], 0, uW2 + jb);
                pass2d(c0, c1, a2[0], a2[1], 2, uW2 + jb + 64);
            }
            #pragma unroll
            for (int tt = 0; tt < 2; tt++) {
                a3[tt][m][0] = f16r(c[0][tt][0], c[0][tt][1]);
                a3[tt][m][1] = f16r(c[0][tt][2], c[0][tt][3]);
                a3[tt][m][2] = f16r(c[1][tt][0], c[1][tt][1]);
                a3[tt][m][3] = f16r(c[1][tt][2], c[1][tt][3]);
            }
        }
        {   // sigma n-tile
            float c0[4], c1[4];
            const float2 bb = *(const float2*)(sB2 + 64 + t2);
            c0[0] = bb.x; c0[1] = bb.y; c0[2] = bb.x; c0[3] = bb.y;
            c1[0] = bb.x; c1[1] = bb.y; c1[2] = bb.x; c1[3] = bb.y;
            const uint32_t jb = 8 * (8 * 144);
            pass2d(c0, c1, a2[0], a2[1], 0, uW2 + jb);
            pass2d(c0, c1, a2[0], a2[1], 2, uW2 + jb + 64);
            if ((lane & 3) == 0) {
                out[t0 * 16 + g]     = __expf(c0[0]);
                out[t0 * 16 + g + 8] = __expf(c0[2]);
                out[t1 * 16 + g]     = __expf(c1[0]);
                out[t1 * 16 + g + 8] = __expf(c1[2]);
            }
        }
        ldsm4(a3[0][4], uSt0 + aofs + 96);
        ldsm4(a3[1][4], uSt1 + aofs + 96);

        // ---------------- L3 ----------------
        uint32_t a4[2][4][4];
        #pragma unroll
        for (int m = 0; m < 4; m++) {
            float c[2][2][4];
            #pragma unroll
            for (int u = 0; u < 2; u++) {
                const uint32_t jb = (2 * m + u) * (8 * 176);
                float *c0 = c[u][0], *c1 = c[u][1];
                #pragma unroll
                for (int q = 0; q < 4; q++) { c0[q] = 0.0f; c1[q] = 0.0f; }
                pass2d(c0, c1, a3[0], a3[1], 0, uW3 + jb);
                pass2d(c0, c1, a3[0], a3[1], 2, uW3 + jb + 64);
                pass1d(c0, c1, a3[0][4], a3[1][4], uW3b + jb);
            }
            #pragma unroll
            for (int tt = 0; tt < 2; tt++) {
                a4[tt][m][0] = f16r(c[0][tt][0], c[0][tt][1]);
                a4[tt][m][1] = f16r(c[0][tt][2], c[0][tt][3]);
                a4[tt][m][2] = f16r(c[1][tt][0], c[1][tt][1]);
                a4[tt][m][3] = f16r(c[1][tt][2], c[1][tt][3]);
            }
        }

        // ---------------- L4 + rgb ----------------
        {
            float c0[4], c1[4];
            const float2 bb = *(const float2*)(sB4 + t2);
            c0[0] = bb.x; c0[1] = bb.y; c0[2] = bb.x; c0[3] = bb.y;
            c1[0] = bb.x; c1[1] = bb.y; c1[2] = bb.x; c1[3] = bb.y;
            pass2d(c0, c1, a4[0], a4[1], 0, uW4);
            pass2d(c0, c1, a4[0], a4[1], 2, uW4 + 64);
            const int p0 = t0 * 16 + g, p1 = t1 * 16 + g;
            if ((lane & 3) == 0) {
                out[n + 3 * p0 + 0]       = sigmoidf_(c0[0]);
                out[n + 3 * p0 + 1]       = sigmoidf_(c0[1]);
                out[n + 3 * (p0 + 8) + 0] = sigmoidf_(c0[2]);
                out[n + 3 * (p0 + 8) + 1] = sigmoidf_(c0[3]);
                out[n + 3 * p1 + 0]       = sigmoidf_(c1[0]);
                out[n + 3 * p1 + 1]       = sigmoidf_(c1[1]);
                out[n + 3 * (p1 + 8) + 0] = sigmoidf_(c1[2]);
                out[n + 3 * (p1 + 8) + 1] = sigmoidf_(c1[3]);
            } else if ((lane & 3) == 1) {
                out[n + 3 * p0 + 2]       = sigmoidf_(c0[0]);
                out[n + 3 * (p0 + 8) + 2] = sigmoidf_(c0[2]);
                out[n + 3 * p1 + 2]       = sigmoidf_(c1[0]);
                out[n + 3 * (p1 + 8) + 2] = sigmoidf_(c1[2]);
            }
        }
        __syncwarp();
    }
}

extern "C" void kernel_launch(void* const* d_in, const int* in_sizes, int n_in,
                              void* d_out, int out_size)
{
    const float* x     = (const float*)d_in[0];
    const float* v     = (const float*)d_in[1];
    const float* table = (const float*)d_in[3];
    const float* dw1   = (const float*)d_in[4];
    const float* db1   = (const float*)d_in[5];
    const float* dw2   = (const float*)d_in[6];
    const float* db2   = (const float*)d_in[7];
    const float* rw1   = (const float*)d_in[8];
    const float* rb1   = (const float*)d_in[9];
    const float* rw2   = (const float*)d_in[10];
    const float* rb2   = (const float*)d_in[11];
    float* out = (float*)d_out;

    const int n = in_sizes[0] / 3;

    cudaFuncSetAttribute(nerf_mma10, cudaFuncAttributeMaxDynamicSharedMemorySize, SMEM_DYN);

    prep_weights<<<1, 256>>>(dw1, db1, dw2, db2, rw1, rb1, rw2, rb2);
    nerf_mma10<<<296, 256, SMEM_DYN>>>(x, v, table, out, n);
}